// round 2
// baseline (speedup 1.0000x reference)
#include <cuda_runtime.h>

// Problem constants
#define BT     16384        // B*T
#define S_DIM  256
#define O_DIM  128
#define N_DIM  32
#define NQ_DIM 64
#define H_DIM  4
#define E_DIM  32
#define NOUT   160          // 128 q outputs (h*32+e) + 32 bias-MLP hidden
#define MASK_VAL (-999999.0f)
#define INV_SQRT_E 0.17677669529663687f

// Scratch (device globals; no allocation allowed)
__device__ float g_qh[(size_t)BT * 128];   // relu(st @ Wq^T), [bt][h*32+e]
__device__ float g_v[BT];                  // bias MLP output per row
__device__ float g_p[(size_t)BT * 512];    // p[bt][h*128+o] = sum_e q*Wk

// ---------------- packed f32x2 helpers ----------------
static __device__ __forceinline__ unsigned long long fma2(unsigned long long a,
                                                          unsigned long long b,
                                                          unsigned long long c) {
    unsigned long long d;
    asm("fma.rn.f32x2 %0, %1, %2, %3;" : "=l"(d) : "l"(a), "l"(b), "l"(c));
    return d;
}
static __device__ __forceinline__ unsigned long long dup2(float w) {
    unsigned long long d;
    asm("mov.b64 %0, {%1, %1};" : "=l"(d) : "f"(w));
    return d;
}
static __device__ __forceinline__ float lo2(unsigned long long v) {
    return __uint_as_float((unsigned int)v);
}
static __device__ __forceinline__ float hi2(unsigned long long v) {
    return __uint_as_float((unsigned int)(v >> 32));
}

// ==================== K1: qh = relu([Wq;Sb_w1] @ st^T), v = MLP(st) ====================
// M=128 rows/CTA, N=160, K=256 in 8 chunks of 32.
// A staged transposed As[k][row] (row pairs -> LDS.64 for f32x2 A operand).
// W staged duplicated Ws[k][n] = (w,w) as u64 (LDS.64 B operand, lane-consecutive).
#define K1_BM 128
#define K1_KC 32
#define K1_AS 130     // As row stride (floats)
#define K1_WS 161     // Ws row stride (u64)
#define K1_SMEM (K1_KC*K1_AS*4 + K1_KC*K1_WS*8)   // 16640 + 41216 = 57856B

__global__ void __launch_bounds__(256) k1_qh(
        const float* __restrict__ st,
        const float* __restrict__ Wq,
        const float* __restrict__ Sw1,
        const float* __restrict__ Sb1,
        const float* __restrict__ Sw2,
        const float* __restrict__ Sb2) {
    extern __shared__ float smem[];
    float* As = smem;                                                   // [32][130]
    unsigned long long* Ws = (unsigned long long*)(smem + K1_KC * K1_AS); // [32][161]

    const int tid = threadIdx.x;
    const int rt  = tid >> 5;     // 8 row groups of 16 rows
    const int ct  = tid & 31;     // 32 col groups; cols {ct, ct+32, ct+64, ct+96, 128+ct}
    const int row0 = blockIdx.x * K1_BM;

    unsigned long long acc[8][5];
#pragma unroll
    for (int i = 0; i < 8; i++)
#pragma unroll
        for (int j = 0; j < 5; j++) acc[i][j] = 0ULL;

    for (int kc = 0; kc < S_DIM; kc += K1_KC) {
        __syncthreads();
        // stage A chunk transposed: As[k][row]
        for (int i = tid; i < (K1_BM * K1_KC) / 4; i += 256) {
            int row = i >> 3, kq = i & 7;
            float4 v = *(const float4*)(st + (size_t)(row0 + row) * S_DIM + kc + kq * 4);
            As[(4 * kq + 0) * K1_AS + row] = v.x;
            As[(4 * kq + 1) * K1_AS + row] = v.y;
            As[(4 * kq + 2) * K1_AS + row] = v.z;
            As[(4 * kq + 3) * K1_AS + row] = v.w;
        }
        // stage W chunk, duplicated: Ws[k][n] = (w,w)
        for (int i = tid; i < NOUT * K1_KC; i += 256) {
            int n = i >> 5, k = i & 31;
            float w = (n < 128) ? Wq[n * S_DIM + kc + k]
                                : Sw1[(n - 128) * S_DIM + kc + k];
            Ws[k * K1_WS + n] = dup2(w);
        }
        __syncthreads();
#pragma unroll 8
        for (int kk = 0; kk < K1_KC; kk++) {
            const float* ar = As + kk * K1_AS + rt * 16;
            const unsigned long long* wr = Ws + kk * K1_WS;
            unsigned long long b0 = wr[ct];
            unsigned long long b1 = wr[32 + ct];
            unsigned long long b2 = wr[64 + ct];
            unsigned long long b3 = wr[96 + ct];
            unsigned long long b4 = wr[128 + ct];
#pragma unroll
            for (int i = 0; i < 8; i++) {
                unsigned long long a = *(const unsigned long long*)(ar + 2 * i);
                acc[i][0] = fma2(a, b0, acc[i][0]);
                acc[i][1] = fma2(a, b1, acc[i][1]);
                acc[i][2] = fma2(a, b2, acc[i][2]);
                acc[i][3] = fma2(a, b3, acc[i][3]);
                acc[i][4] = fma2(a, b4, acc[i][4]);
            }
        }
    }

    // epilogue: relu q -> g_qh; bias MLP -> g_v
    const float b1c = Sb1[ct];
    const float w2c = Sw2[ct];
    const float b2c = Sb2[0];
#pragma unroll
    for (int i = 0; i < 8; i++) {
        int r0 = row0 + rt * 16 + 2 * i;
#pragma unroll
        for (int j = 0; j < 4; j++) {
            g_qh[(size_t)r0 * 128 + ct + 32 * j]       = fmaxf(lo2(acc[i][j]), 0.0f);
            g_qh[(size_t)(r0 + 1) * 128 + ct + 32 * j] = fmaxf(hi2(acc[i][j]), 0.0f);
        }
        float h0 = fmaxf(lo2(acc[i][4]) + b1c, 0.0f) * w2c;
        float h1 = fmaxf(hi2(acc[i][4]) + b1c, 0.0f) * w2c;
#pragma unroll
        for (int d = 16; d > 0; d >>= 1) {
            h0 += __shfl_xor_sync(0xffffffffu, h0, d);
            h1 += __shfl_xor_sync(0xffffffffu, h1, d);
        }
        if (ct == 0) {
            g_v[r0]     = h0 + b2c;
            g_v[r0 + 1] = h1 + b2c;
        }
    }
}

// ==================== K2: p[r][h*128+o] = sum_e qh[r][h*32+e] * Wk[h][e][o] ====================
// M=64 rows/CTA. qh staged transposed (row-pair LDS.64).
// Wk staged as plain floats (64KB); (w,w) dup built in registers.
#define K2_BM 64
#define K2_QT 66      // qhT row stride (floats)
#define K2_SMEM (128*K2_QT*4 + 16384*4)   // 33792 + 65536 = 99328B

__global__ void __launch_bounds__(256) k2_p(const float* __restrict__ Wk) {
    extern __shared__ float smem2[];
    float* qhT  = smem2;                     // [128][66]
    float* wk_s = smem2 + 128 * K2_QT;       // [4][32][128] floats

    const int tid = threadIdx.x;
    const int rt  = tid >> 5;    // 8 groups of 8 rows
    const int ct  = tid & 31;    // o cols {ct, ct+32, ct+64, ct+96}
    const int row0 = blockIdx.x * K2_BM;

    for (int i = tid; i < (K2_BM * 128) / 4; i += 256) {
        int r = i >> 5, cq = i & 31;
        float4 v = *(const float4*)(g_qh + (size_t)(row0 + r) * 128 + 4 * cq);
        qhT[(4 * cq + 0) * K2_QT + r] = v.x;
        qhT[(4 * cq + 1) * K2_QT + r] = v.y;
        qhT[(4 * cq + 2) * K2_QT + r] = v.z;
        qhT[(4 * cq + 3) * K2_QT + r] = v.w;
    }
    for (int i = tid; i < 16384 / 4; i += 256)
        ((float4*)wk_s)[i] = ((const float4*)Wk)[i];
    __syncthreads();

#pragma unroll
    for (int h = 0; h < 4; h++) {
        unsigned long long acc[4][4];
#pragma unroll
        for (int i = 0; i < 4; i++)
#pragma unroll
            for (int j = 0; j < 4; j++) acc[i][j] = 0ULL;

#pragma unroll 8
        for (int e = 0; e < 32; e++) {
            const float* ar = qhT + (h * 32 + e) * K2_QT + rt * 8;
            const float* br = wk_s + (h * 32 + e) * 128;
            unsigned long long b0 = dup2(br[ct]);
            unsigned long long b1 = dup2(br[32 + ct]);
            unsigned long long b2 = dup2(br[64 + ct]);
            unsigned long long b3 = dup2(br[96 + ct]);
#pragma unroll
            for (int i = 0; i < 4; i++) {
                unsigned long long a = *(const unsigned long long*)(ar + 2 * i);
                acc[i][0] = fma2(a, b0, acc[i][0]);
                acc[i][1] = fma2(a, b1, acc[i][1]);
                acc[i][2] = fma2(a, b2, acc[i][2]);
                acc[i][3] = fma2(a, b3, acc[i][3]);
            }
        }
#pragma unroll
        for (int i = 0; i < 4; i++) {
            int r0 = row0 + rt * 8 + 2 * i;
#pragma unroll
            for (int j = 0; j < 4; j++) {
                g_p[(size_t)r0 * 512 + h * 128 + ct + 32 * j]       = lo2(acc[i][j]);
                g_p[(size_t)(r0 + 1) * 512 + h * 128 + ct + 32 * j] = hi2(acc[i][j]);
            }
        }
    }
}

// ==================== K3: per-row scores/softmax/output ====================
// 1 CTA (128 thr) per bt row. scores[h][n] = (1/sqrt(E)) * sum_o p[h][o]*ob[n][o]
__global__ void __launch_bounds__(128) k3_out(
        const float* __restrict__ z,
        const float* __restrict__ obs,
        float* __restrict__ out) {
    __shared__ float ob_s[32 * 129];                 // pad 129 (odd) -> conflict-free
    __shared__ float z_s[32 * 65];                   // pad 65 (odd)
    __shared__ __align__(16) float p_s[512];
    __shared__ float part_s[4][4][32];
    __shared__ float att_s[128];
    __shared__ float w_s[32];
    __shared__ float qv_s[32];
    __shared__ float v_sh;

    const int tid = threadIdx.x;
    const size_t r = blockIdx.x;
    const float* zr  = z + r * (size_t)(N_DIM * NQ_DIM);
    const float* obr = obs + r * (size_t)(N_DIM * O_DIM);

    for (int i = tid; i < 512; i += 128) {           // z: 32x64 floats
        float4 v = ((const float4*)zr)[i];
        int n = i >> 4, jq = i & 15;
        z_s[n * 65 + 4 * jq + 0] = v.x;
        z_s[n * 65 + 4 * jq + 1] = v.y;
        z_s[n * 65 + 4 * jq + 2] = v.z;
        z_s[n * 65 + 4 * jq + 3] = v.w;
    }
    for (int i = tid; i < 1024; i += 128) {          // ob: 32x128 floats
        float4 v = ((const float4*)obr)[i];
        int n = i >> 5, oq = i & 31;
        ob_s[n * 129 + 4 * oq + 0] = v.x;
        ob_s[n * 129 + 4 * oq + 1] = v.y;
        ob_s[n * 129 + 4 * oq + 2] = v.z;
        ob_s[n * 129 + 4 * oq + 3] = v.w;
    }
    for (int i = tid; i < 512; i += 128) p_s[i] = g_p[r * 512 + i];
    if (tid == 0) v_sh = g_v[r];
    __syncthreads();

    if (tid < 32) {                                   // q_vals[n] = mean_q z[n][q]
        float s = 0.0f;
        for (int j = 0; j < 64; j++) s += z_s[tid * 65 + j];
        qv_s[tid] = s * (1.0f / 64.0f);
    }

    // partial scores: thread (n, oq) covers o in [32*oq, 32*oq+32)
    const int n  = tid & 31;
    const int oq = tid >> 5;
    float pa0 = 0.0f, pa1 = 0.0f, pa2 = 0.0f, pa3 = 0.0f;
    const float* obn = ob_s + n * 129 + oq * 32;
    const float* pb  = p_s + oq * 32;
#pragma unroll
    for (int o4 = 0; o4 < 8; o4++) {
        float x0 = obn[4 * o4 + 0], x1 = obn[4 * o4 + 1];
        float x2 = obn[4 * o4 + 2], x3 = obn[4 * o4 + 3];
        float4 p0 = *(const float4*)(pb + 0   + 4 * o4);
        float4 p1 = *(const float4*)(pb + 128 + 4 * o4);
        float4 p2 = *(const float4*)(pb + 256 + 4 * o4);
        float4 p3 = *(const float4*)(pb + 384 + 4 * o4);
        pa0 += x0 * p0.x + x1 * p0.y + x2 * p0.z + x3 * p0.w;
        pa1 += x0 * p1.x + x1 * p1.y + x2 * p1.z + x3 * p1.w;
        pa2 += x0 * p2.x + x1 * p2.y + x2 * p2.z + x3 * p2.w;
        pa3 += x0 * p3.x + x1 * p3.y + x2 * p3.z + x3 * p3.w;
    }
    part_s[oq][0][n] = pa0;
    part_s[oq][1][n] = pa1;
    part_s[oq][2][n] = pa2;
    part_s[oq][3][n] = pa3;
    __syncthreads();

    // scores -> mask -> softmax (warp h = tid>>5 handles n = lane)
    const int h = tid >> 5;
    float s = part_s[0][h][n] + part_s[1][h][n] + part_s[2][h][n] + part_s[3][h][n];
    s *= INV_SQRT_E;
    if (qv_s[n] <= MASK_VAL) s = MASK_VAL;
    float m = s;
#pragma unroll
    for (int d = 16; d > 0; d >>= 1) m = fmaxf(m, __shfl_xor_sync(0xffffffffu, m, d));
    float ex = __expf(s - m);
    float ssum = ex;
#pragma unroll
    for (int d = 16; d > 0; d >>= 1) ssum += __shfl_xor_sync(0xffffffffu, ssum, d);
    att_s[h * 32 + n] = ex / ssum;
    __syncthreads();

    if (tid < 32)
        w_s[tid] = att_s[tid] + att_s[32 + tid] + att_s[64 + tid] + att_s[96 + tid] + 1e-10f;
    __syncthreads();

    if (tid < 64) {                                   // out[q] = sum_n w[n]*z[n][q] + N*v
        float acc = (float)N_DIM * v_sh;
#pragma unroll
        for (int nn = 0; nn < 32; nn++) acc = fmaf(w_s[nn], z_s[nn * 65 + tid], acc);
        out[r * 64 + tid] = acc;
    }
}

// ==================== launch ====================
extern "C" void kernel_launch(void* const* d_in, const int* in_sizes, int n_in,
                              void* d_out, int out_size) {
    (void)in_sizes; (void)n_in; (void)out_size;
    const float* z   = (const float*)d_in[0];
    const float* st  = (const float*)d_in[1];
    const float* obs = (const float*)d_in[2];
    const float* Wq  = (const float*)d_in[3];
    const float* Wk  = (const float*)d_in[4];
    const float* Sw1 = (const float*)d_in[5];
    const float* Sb1 = (const float*)d_in[6];
    const float* Sw2 = (const float*)d_in[7];
    const float* Sb2 = (const float*)d_in[8];
    float* out = (float*)d_out;

    cudaFuncSetAttribute(k1_qh, cudaFuncAttributeMaxDynamicSharedMemorySize, K1_SMEM);
    cudaFuncSetAttribute(k2_p,  cudaFuncAttributeMaxDynamicSharedMemorySize, K2_SMEM);

    k1_qh<<<BT / K1_BM, 256, K1_SMEM>>>(st, Wq, Sw1, Sb1, Sw2, Sb2);
    k2_p<<<BT / K2_BM, 256, K2_SMEM>>>(Wk);
    k3_out<<<BT, 128>>>(z, obs, out);
}

// round 4
// speedup vs baseline: 1.5482x; 1.5482x over previous
#include <cuda_runtime.h>

// Problem constants
#define BT     16384
#define S_DIM  256
#define O_DIM  128
#define N_DIM  32
#define NQ_DIM 64
#define NOUT   160
#define MASK_VAL (-999999.0f)
#define INV_SQRT_E 0.17677669529663687f

// Scratch (device globals; no allocation allowed)
__device__ float g_qh[(size_t)BT * 128];   // relu(st @ Wq^T), [bt][h*32+e]
__device__ float g_v[BT];                  // bias MLP output per row
__device__ float g_p[(size_t)BT * 512];    // p[bt][h*128+o]

// ---------------- packed f32x2 helpers ----------------
static __device__ __forceinline__ unsigned long long fma2(unsigned long long a,
                                                          unsigned long long b,
                                                          unsigned long long c) {
    unsigned long long d;
    asm("fma.rn.f32x2 %0, %1, %2, %3;" : "=l"(d) : "l"(a), "l"(b), "l"(c));
    return d;
}
static __device__ __forceinline__ unsigned long long dup2(float w) {
    unsigned long long d;
    asm("mov.b64 %0, {%1, %1};" : "=l"(d) : "f"(w));
    return d;
}
static __device__ __forceinline__ float lo2(unsigned long long v) {
    return __uint_as_float((unsigned int)v);
}
static __device__ __forceinline__ float hi2(unsigned long long v) {
    return __uint_as_float((unsigned int)(v >> 32));
}

// ==================== K1: qh = relu([Wq;Sb_w1] @ st^T), v = MLP(st) ====================
// BM=32 rows/CTA -> grid 512. A transposed As[k][row] (u64 row-pair loads are
// warp-uniform broadcasts). W staged [n][k] stride 33, dup built in registers.
#define K1_BM 32
#define K1_KC 32
#define K1_AS 34                       // As stride (even -> u64 aligned)
#define K1_WS 33                       // Ws stride
#define K1_SMEM (K1_KC*K1_AS*4 + NOUT*K1_WS*4)   // 4352 + 21120 = 25472B

__global__ void __launch_bounds__(256) k1_qh(
        const float* __restrict__ st,
        const float* __restrict__ Wq,
        const float* __restrict__ Sw1,
        const float* __restrict__ Sb1,
        const float* __restrict__ Sw2,
        const float* __restrict__ Sb2) {
    extern __shared__ float smem[];
    float* As = smem;                          // [32 k][34]
    float* Ws = smem + K1_KC * K1_AS;          // [160 n][33]

    const int tid = threadIdx.x;
    const int rt  = tid >> 5;     // 8 groups of 4 rows
    const int ct  = tid & 31;
    const int row0 = blockIdx.x * K1_BM;

    unsigned long long acc[2][5];
#pragma unroll
    for (int i = 0; i < 2; i++)
#pragma unroll
        for (int j = 0; j < 5; j++) acc[i][j] = 0ULL;

    for (int kc = 0; kc < S_DIM; kc += K1_KC) {
        __syncthreads();
        // stage A transposed (32 rows x 32 k) -- 256 float4, one per thread
        {
            int row = tid >> 3, kq = tid & 7;
            float4 v = *(const float4*)(st + (size_t)(row0 + row) * S_DIM + kc + 4 * kq);
            As[(4 * kq + 0) * K1_AS + row] = v.x;
            As[(4 * kq + 1) * K1_AS + row] = v.y;
            As[(4 * kq + 2) * K1_AS + row] = v.z;
            As[(4 * kq + 3) * K1_AS + row] = v.w;
        }
        // stage W [n][k] (160 n x 32 k) = 1280 float4
        for (int i = tid; i < (NOUT * K1_KC) / 4; i += 256) {
            int n = i >> 3, kq = i & 7;
            const float* src = (n < 128) ? (Wq + n * S_DIM) : (Sw1 + (n - 128) * S_DIM);
            float4 v = *(const float4*)(src + kc + 4 * kq);
            Ws[n * K1_WS + 4 * kq + 0] = v.x;
            Ws[n * K1_WS + 4 * kq + 1] = v.y;
            Ws[n * K1_WS + 4 * kq + 2] = v.z;
            Ws[n * K1_WS + 4 * kq + 3] = v.w;
        }
        __syncthreads();
#pragma unroll 8
        for (int kk = 0; kk < K1_KC; kk++) {
            unsigned long long b0 = dup2(Ws[(ct)       * K1_WS + kk]);
            unsigned long long b1 = dup2(Ws[(ct + 32)  * K1_WS + kk]);
            unsigned long long b2 = dup2(Ws[(ct + 64)  * K1_WS + kk]);
            unsigned long long b3 = dup2(Ws[(ct + 96)  * K1_WS + kk]);
            unsigned long long b4 = dup2(Ws[(ct + 128) * K1_WS + kk]);
            const float* ar = As + kk * K1_AS + rt * 4;
#pragma unroll
            for (int i = 0; i < 2; i++) {
                unsigned long long a = *(const unsigned long long*)(ar + 2 * i);
                acc[i][0] = fma2(a, b0, acc[i][0]);
                acc[i][1] = fma2(a, b1, acc[i][1]);
                acc[i][2] = fma2(a, b2, acc[i][2]);
                acc[i][3] = fma2(a, b3, acc[i][3]);
                acc[i][4] = fma2(a, b4, acc[i][4]);
            }
        }
    }

    const float b1c = Sb1[ct];
    const float w2c = Sw2[ct];
    const float b2c = Sb2[0];
#pragma unroll
    for (int i = 0; i < 2; i++) {
        int r0 = row0 + rt * 4 + 2 * i;
#pragma unroll
        for (int j = 0; j < 4; j++) {
            g_qh[(size_t)r0 * 128 + ct + 32 * j]       = fmaxf(lo2(acc[i][j]), 0.0f);
            g_qh[(size_t)(r0 + 1) * 128 + ct + 32 * j] = fmaxf(hi2(acc[i][j]), 0.0f);
        }
        float h0 = fmaxf(lo2(acc[i][4]) + b1c, 0.0f) * w2c;
        float h1 = fmaxf(hi2(acc[i][4]) + b1c, 0.0f) * w2c;
#pragma unroll
        for (int d = 16; d > 0; d >>= 1) {
            h0 += __shfl_xor_sync(0xffffffffu, h0, d);
            h1 += __shfl_xor_sync(0xffffffffu, h1, d);
        }
        if (ct == 0) {
            g_v[r0]     = h0 + b2c;
            g_v[r0 + 1] = h1 + b2c;
        }
    }
}

// ==================== K2: p[r][h*128+o] = sum_e qh[r][h*32+e] * Wk[h][e][o] ====================
// Pairs on O axis: B = adjacent Wk u64 (flat copy, no transpose), A = dup2 of
// warp-uniform qh broadcast. BM=64 -> grid 256, coalesced STG.64 output.
#define K2_BM 64
#define K2_SMEM (K2_BM*128*4 + 16384*4)    // 32768 + 65536 = 98304B

__global__ void __launch_bounds__(256) k2_p(const float* __restrict__ Wk) {
    extern __shared__ float smem2[];
    float* qh_s = smem2;                                      // [64][128]
    unsigned long long* wk2 = (unsigned long long*)(smem2 + K2_BM * 128); // [128 he][64 pairs]

    const int tid = threadIdx.x;
    const int rt  = tid >> 5;          // 8 groups of 8 rows
    const int ct  = tid & 31;          // o-pairs: ct and ct+32
    const int row0 = blockIdx.x * K2_BM;

    for (int i = tid; i < (K2_BM * 128) / 4; i += 256)        // 2048 float4
        ((float4*)qh_s)[i] = *(const float4*)(g_qh + (size_t)row0 * 128 + 4 * i);
    for (int i = tid; i < 16384 / 4; i += 256)                // 4096 float4
        ((float4*)wk2)[i] = ((const float4*)Wk)[i];
    __syncthreads();

    unsigned long long* gp2 = (unsigned long long*)g_p;
#pragma unroll
    for (int h = 0; h < 4; h++) {
        unsigned long long acc[8][2];
#pragma unroll
        for (int rr = 0; rr < 8; rr++) { acc[rr][0] = 0ULL; acc[rr][1] = 0ULL; }

#pragma unroll 2
        for (int e4 = 0; e4 < 8; e4++) {
            float4 aq[8];
#pragma unroll
            for (int rr = 0; rr < 8; rr++)
                aq[rr] = *(const float4*)(qh_s + (rt * 8 + rr) * 128 + h * 32 + 4 * e4);
#pragma unroll
            for (int q = 0; q < 4; q++) {
                const unsigned long long* brow = wk2 + (size_t)(h * 32 + 4 * e4 + q) * 64;
                unsigned long long b0 = brow[ct];
                unsigned long long b1 = brow[32 + ct];
#pragma unroll
                for (int rr = 0; rr < 8; rr++) {
                    float av = (q == 0) ? aq[rr].x : (q == 1) ? aq[rr].y
                             : (q == 2) ? aq[rr].z : aq[rr].w;
                    unsigned long long a = dup2(av);
                    acc[rr][0] = fma2(a, b0, acc[rr][0]);
                    acc[rr][1] = fma2(a, b1, acc[rr][1]);
                }
            }
        }
#pragma unroll
        for (int rr = 0; rr < 8; rr++) {
            size_t base = ((size_t)(row0 + rt * 8 + rr) * 512 + h * 128) >> 1;
            gp2[base + ct]      = acc[rr][0];
            gp2[base + 32 + ct] = acc[rr][1];
        }
    }
}

// ==================== K3: per-row scores/softmax/output ====================
__global__ void __launch_bounds__(128) k3_out(
        const float* __restrict__ z,
        const float* __restrict__ obs,
        float* __restrict__ out) {
    __shared__ float4 obf4[32 * 33];           // ob[n][c4], pad 33
    __shared__ float4 zf4[32 * 17];            // z[n][j4], pad 17
    __shared__ __align__(16) float p_s[512];
    __shared__ float part_s[4][4][32];
    __shared__ float att_s[128];
    __shared__ float w_s[32];
    __shared__ float qv_s[32];
    __shared__ float v_sh;

    const int tid = threadIdx.x;
    const size_t r = blockIdx.x;
    const float4* zr4  = (const float4*)(z + r * (size_t)(N_DIM * NQ_DIM));
    const float4* obr4 = (const float4*)(obs + r * (size_t)(N_DIM * O_DIM));

    // z load (512 float4) fused with q_vals partial sums
    float part[4];
#pragma unroll
    for (int seg = 0; seg < 4; seg++) {
        int i = tid + 128 * seg;               // i < 512
        int n = i >> 4, jq = i & 15;
        float4 v = zr4[i];
        zf4[n * 17 + jq] = v;
        part[seg] = v.x + v.y + v.z + v.w;
    }
#pragma unroll
    for (int d = 8; d > 0; d >>= 1)
#pragma unroll
        for (int seg = 0; seg < 4; seg++)
            part[seg] += __shfl_xor_sync(0xffffffffu, part[seg], d);
    if ((tid & 15) == 0) {
        int n0 = tid >> 4;
#pragma unroll
        for (int seg = 0; seg < 4; seg++)
            qv_s[n0 + 8 * seg] = part[seg] * (1.0f / 64.0f);
    }
    // obs load: 32 rows x 32 float4 = 1024 float4 -> 8 segments of 128
#pragma unroll
    for (int seg = 0; seg < 8; seg++) {
        int i = tid + 128 * seg;               // i < 1024
        int n = i >> 5, c = i & 31;
        obf4[n * 33 + c] = obr4[i];
    }
    ((float4*)p_s)[tid] = ((const float4*)(g_p + r * 512))[tid];
    if (tid == 0) v_sh = g_v[r];
    __syncthreads();

    // scores: thread (n, oq) covers o-chunk [oq*32, oq*32+32)
    const int n  = tid & 31;
    const int oq = tid >> 5;
    const float4* obn = obf4 + n * 33 + oq * 8;
    const float4* pb  = (const float4*)p_s;
    float pa0 = 0.0f, pa1 = 0.0f, pa2 = 0.0f, pa3 = 0.0f;
#pragma unroll
    for (int o4 = 0; o4 < 8; o4++) {
        float4 x  = obn[o4];
        float4 p0 = pb[0  + oq * 8 + o4];
        float4 p1 = pb[32 + oq * 8 + o4];
        float4 p2 = pb[64 + oq * 8 + o4];
        float4 p3 = pb[96 + oq * 8 + o4];
        pa0 += x.x * p0.x + x.y * p0.y + x.z * p0.z + x.w * p0.w;
        pa1 += x.x * p1.x + x.y * p1.y + x.z * p1.z + x.w * p1.w;
        pa2 += x.x * p2.x + x.y * p2.y + x.z * p2.z + x.w * p2.w;
        pa3 += x.x * p3.x + x.y * p3.y + x.z * p3.z + x.w * p3.w;
    }
    part_s[oq][0][n] = pa0;
    part_s[oq][1][n] = pa1;
    part_s[oq][2][n] = pa2;
    part_s[oq][3][n] = pa3;
    __syncthreads();

    // softmax per head-warp
    const int h = tid >> 5;
    float s = part_s[0][h][n] + part_s[1][h][n] + part_s[2][h][n] + part_s[3][h][n];
    s *= INV_SQRT_E;
    if (qv_s[n] <= MASK_VAL) s = MASK_VAL;
    float m = s;
#pragma unroll
    for (int d = 16; d > 0; d >>= 1) m = fmaxf(m, __shfl_xor_sync(0xffffffffu, m, d));
    float ex = __expf(s - m);
    float ssum = ex;
#pragma unroll
    for (int d = 16; d > 0; d >>= 1) ssum += __shfl_xor_sync(0xffffffffu, ssum, d);
    att_s[h * 32 + n] = ex / ssum;
    __syncthreads();

    if (tid < 32)
        w_s[tid] = att_s[tid] + att_s[32 + tid] + att_s[64 + tid] + att_s[96 + tid] + 1e-10f;
    __syncthreads();

    if (tid < 64) {
        const float* zsf = (const float*)zf4;  // row stride 68 floats
        float acc = (float)N_DIM * v_sh;
#pragma unroll
        for (int nn = 0; nn < 32; nn++) acc = fmaf(w_s[nn], zsf[nn * 68 + tid], acc);
        out[r * 64 + tid] = acc;
    }
}

// ==================== launch ====================
extern "C" void kernel_launch(void* const* d_in, const int* in_sizes, int n_in,
                              void* d_out, int out_size) {
    (void)in_sizes; (void)n_in; (void)out_size;
    const float* z   = (const float*)d_in[0];
    const float* st  = (const float*)d_in[1];
    const float* obs = (const float*)d_in[2];
    const float* Wq  = (const float*)d_in[3];
    const float* Wk  = (const float*)d_in[4];
    const float* Sw1 = (const float*)d_in[5];
    const float* Sb1 = (const float*)d_in[6];
    const float* Sw2 = (const float*)d_in[7];
    const float* Sb2 = (const float*)d_in[8];
    float* out = (float*)d_out;

    cudaFuncSetAttribute(k1_qh, cudaFuncAttributeMaxDynamicSharedMemorySize, K1_SMEM);
    cudaFuncSetAttribute(k2_p,  cudaFuncAttributeMaxDynamicSharedMemorySize, K2_SMEM);

    k1_qh<<<BT / K1_BM, 256, K1_SMEM>>>(st, Wq, Sw1, Sb1, Sw2, Sb2);
    k2_p<<<BT / K2_BM, 256, K2_SMEM>>>(Wk);
    k3_out<<<BT, 128>>>(z, obs, out);
}

// round 5
// speedup vs baseline: 1.5880x; 1.0257x over previous
#include <cuda_runtime.h>

// Problem constants
#define BT     16384
#define S_DIM  256
#define O_DIM  128
#define N_DIM  32
#define NQ_DIM 64
#define NOUT   160
#define MASK_VAL (-999999.0f)
#define INV_SQRT_E 0.17677669529663687f

// Scratch (device globals; no allocation allowed)
__device__ float g_qh[(size_t)BT * 128];   // relu(st @ Wq^T), [bt][h*32+e]
__device__ float g_v[BT];                  // bias MLP output per row
__device__ float g_p[(size_t)BT * 512];    // p[bt][h*128+o]

// ---------------- packed f32x2 helpers ----------------
static __device__ __forceinline__ unsigned long long fma2(unsigned long long a,
                                                          unsigned long long b,
                                                          unsigned long long c) {
    unsigned long long d;
    asm("fma.rn.f32x2 %0, %1, %2, %3;" : "=l"(d) : "l"(a), "l"(b), "l"(c));
    return d;
}
static __device__ __forceinline__ unsigned long long dup2(float w) {
    unsigned long long d;
    asm("mov.b64 %0, {%1, %1};" : "=l"(d) : "f"(w));
    return d;
}
static __device__ __forceinline__ float lo2(unsigned long long v) {
    return __uint_as_float((unsigned int)v);
}
static __device__ __forceinline__ float hi2(unsigned long long v) {
    return __uint_as_float((unsigned int)(v >> 32));
}

// ==================== K1: qh = relu([Wq;Sb_w1] @ st^T), v = MLP(st) ====================
// BM=64 rows/CTA -> grid 256. Register blocking: 8 rows x 5 col-groups per
// thread (20 u64 acc). Inner loop: 9 LDS per 20 fma2 (was 7 per 10).
#define K1_BM 64
#define K1_KC 32
#define K1_AS 66                       // As stride (even -> u64 aligned)
#define K1_WS 33                       // Ws stride
#define K1_SMEM (K1_KC*K1_AS*4 + NOUT*K1_WS*4)   // 8448 + 21120 = 29568B

__global__ void __launch_bounds__(256, 3) k1_qh(
        const float* __restrict__ st,
        const float* __restrict__ Wq,
        const float* __restrict__ Sw1,
        const float* __restrict__ Sb1,
        const float* __restrict__ Sw2,
        const float* __restrict__ Sb2) {
    extern __shared__ float smem[];
    float* As = smem;                          // [32 k][66]
    float* Ws = smem + K1_KC * K1_AS;          // [160 n][33]

    const int tid = threadIdx.x;
    const int rt  = tid >> 5;     // 8 groups of 8 rows
    const int ct  = tid & 31;
    const int row0 = blockIdx.x * K1_BM;

    unsigned long long acc[4][5];
#pragma unroll
    for (int i = 0; i < 4; i++)
#pragma unroll
        for (int j = 0; j < 5; j++) acc[i][j] = 0ULL;

    for (int kc = 0; kc < S_DIM; kc += K1_KC) {
        __syncthreads();
        // stage A transposed (64 rows x 32 k) = 512 float4, 2 per thread
#pragma unroll
        for (int s = 0; s < 2; s++) {
            int idx = tid + 256 * s;
            int row = idx >> 3, kq = idx & 7;
            float4 v = *(const float4*)(st + (size_t)(row0 + row) * S_DIM + kc + 4 * kq);
            As[(4 * kq + 0) * K1_AS + row] = v.x;
            As[(4 * kq + 1) * K1_AS + row] = v.y;
            As[(4 * kq + 2) * K1_AS + row] = v.z;
            As[(4 * kq + 3) * K1_AS + row] = v.w;
        }
        // stage W [n][k] (160 n x 32 k) = 1280 float4
        for (int i = tid; i < (NOUT * K1_KC) / 4; i += 256) {
            int n = i >> 3, kq = i & 7;
            const float* src = (n < 128) ? (Wq + n * S_DIM) : (Sw1 + (n - 128) * S_DIM);
            float4 v = *(const float4*)(src + kc + 4 * kq);
            Ws[n * K1_WS + 4 * kq + 0] = v.x;
            Ws[n * K1_WS + 4 * kq + 1] = v.y;
            Ws[n * K1_WS + 4 * kq + 2] = v.z;
            Ws[n * K1_WS + 4 * kq + 3] = v.w;
        }
        __syncthreads();
#pragma unroll 8
        for (int kk = 0; kk < K1_KC; kk++) {
            unsigned long long b0 = dup2(Ws[(ct)       * K1_WS + kk]);
            unsigned long long b1 = dup2(Ws[(ct + 32)  * K1_WS + kk]);
            unsigned long long b2 = dup2(Ws[(ct + 64)  * K1_WS + kk]);
            unsigned long long b3 = dup2(Ws[(ct + 96)  * K1_WS + kk]);
            unsigned long long b4 = dup2(Ws[(ct + 128) * K1_WS + kk]);
            const float* ar = As + kk * K1_AS + rt * 8;
#pragma unroll
            for (int i = 0; i < 4; i++) {
                unsigned long long a = *(const unsigned long long*)(ar + 2 * i);
                acc[i][0] = fma2(a, b0, acc[i][0]);
                acc[i][1] = fma2(a, b1, acc[i][1]);
                acc[i][2] = fma2(a, b2, acc[i][2]);
                acc[i][3] = fma2(a, b3, acc[i][3]);
                acc[i][4] = fma2(a, b4, acc[i][4]);
            }
        }
    }

    const float b1c = Sb1[ct];
    const float w2c = Sw2[ct];
    const float b2c = Sb2[0];
#pragma unroll
    for (int i = 0; i < 4; i++) {
        int r0 = row0 + rt * 8 + 2 * i;
#pragma unroll
        for (int j = 0; j < 4; j++) {
            g_qh[(size_t)r0 * 128 + ct + 32 * j]       = fmaxf(lo2(acc[i][j]), 0.0f);
            g_qh[(size_t)(r0 + 1) * 128 + ct + 32 * j] = fmaxf(hi2(acc[i][j]), 0.0f);
        }
        float h0 = fmaxf(lo2(acc[i][4]) + b1c, 0.0f) * w2c;
        float h1 = fmaxf(hi2(acc[i][4]) + b1c, 0.0f) * w2c;
#pragma unroll
        for (int d = 16; d > 0; d >>= 1) {
            h0 += __shfl_xor_sync(0xffffffffu, h0, d);
            h1 += __shfl_xor_sync(0xffffffffu, h1, d);
        }
        if (ct == 0) {
            g_v[r0]     = h0 + b2c;
            g_v[r0 + 1] = h1 + b2c;
        }
    }
}

// ==================== K2: p[r][h*128+o] = sum_e qh[r][h*32+e] * Wk[h][e][o] ====================
#define K2_BM 64
#define K2_SMEM (K2_BM*128*4 + 16384*4)    // 32768 + 65536 = 98304B

__global__ void __launch_bounds__(256) k2_p(const float* __restrict__ Wk) {
    extern __shared__ float smem2[];
    float* qh_s = smem2;                                      // [64][128]
    unsigned long long* wk2 = (unsigned long long*)(smem2 + K2_BM * 128); // [128 he][64 pairs]

    const int tid = threadIdx.x;
    const int rt  = tid >> 5;          // 8 groups of 8 rows
    const int ct  = tid & 31;          // o-pairs: ct and ct+32
    const int row0 = blockIdx.x * K2_BM;

    for (int i = tid; i < (K2_BM * 128) / 4; i += 256)        // 2048 float4
        ((float4*)qh_s)[i] = *(const float4*)(g_qh + (size_t)row0 * 128 + 4 * i);
    for (int i = tid; i < 16384 / 4; i += 256)                // 4096 float4
        ((float4*)wk2)[i] = ((const float4*)Wk)[i];
    __syncthreads();

    unsigned long long* gp2 = (unsigned long long*)g_p;
#pragma unroll
    for (int h = 0; h < 4; h++) {
        unsigned long long acc[8][2];
#pragma unroll
        for (int rr = 0; rr < 8; rr++) { acc[rr][0] = 0ULL; acc[rr][1] = 0ULL; }

#pragma unroll 2
        for (int e4 = 0; e4 < 8; e4++) {
            float4 aq[8];
#pragma unroll
            for (int rr = 0; rr < 8; rr++)
                aq[rr] = *(const float4*)(qh_s + (rt * 8 + rr) * 128 + h * 32 + 4 * e4);
#pragma unroll
            for (int q = 0; q < 4; q++) {
                const unsigned long long* brow = wk2 + (size_t)(h * 32 + 4 * e4 + q) * 64;
                unsigned long long b0 = brow[ct];
                unsigned long long b1 = brow[32 + ct];
#pragma unroll
                for (int rr = 0; rr < 8; rr++) {
                    float av = (q == 0) ? aq[rr].x : (q == 1) ? aq[rr].y
                             : (q == 2) ? aq[rr].z : aq[rr].w;
                    unsigned long long a = dup2(av);
                    acc[rr][0] = fma2(a, b0, acc[rr][0]);
                    acc[rr][1] = fma2(a, b1, acc[rr][1]);
                }
            }
        }
#pragma unroll
        for (int rr = 0; rr < 8; rr++) {
            size_t base = ((size_t)(row0 + rt * 8 + rr) * 512 + h * 128) >> 1;
            gp2[base + ct]      = acc[rr][0];
            gp2[base + 32 + ct] = acc[rr][1];
        }
    }
}

// ==================== K3: per-row scores/softmax/output ====================
__global__ void __launch_bounds__(128) k3_out(
        const float* __restrict__ z,
        const float* __restrict__ obs,
        float* __restrict__ out) {
    __shared__ float4 obf4[32 * 33];           // ob[n][c4], pad 33
    __shared__ float4 zf4[32 * 17];            // z[n][j4], pad 17
    __shared__ __align__(16) float p_s[512];
    __shared__ float part_s[4][4][32];
    __shared__ float att_s[128];
    __shared__ float w_s[32];
    __shared__ float qv_s[32];
    __shared__ float v_sh;

    const int tid = threadIdx.x;
    const size_t r = blockIdx.x;
    const float4* zr4  = (const float4*)(z + r * (size_t)(N_DIM * NQ_DIM));
    const float4* obr4 = (const float4*)(obs + r * (size_t)(N_DIM * O_DIM));

    // z load (512 float4) fused with q_vals partial sums
    float part[4];
#pragma unroll
    for (int seg = 0; seg < 4; seg++) {
        int i = tid + 128 * seg;               // i < 512
        int n = i >> 4, jq = i & 15;
        float4 v = zr4[i];
        zf4[n * 17 + jq] = v;
        part[seg] = v.x + v.y + v.z + v.w;
    }
#pragma unroll
    for (int d = 8; d > 0; d >>= 1)
#pragma unroll
        for (int seg = 0; seg < 4; seg++)
            part[seg] += __shfl_xor_sync(0xffffffffu, part[seg], d);
    if ((tid & 15) == 0) {
        int n0 = tid >> 4;
#pragma unroll
        for (int seg = 0; seg < 4; seg++)
            qv_s[n0 + 8 * seg] = part[seg] * (1.0f / 64.0f);
    }
    // obs load: 32 rows x 32 float4 = 1024 float4 -> 8 segments of 128
#pragma unroll
    for (int seg = 0; seg < 8; seg++) {
        int i = tid + 128 * seg;               // i < 1024
        int n = i >> 5, c = i & 31;
        obf4[n * 33 + c] = obr4[i];
    }
    ((float4*)p_s)[tid] = ((const float4*)(g_p + r * 512))[tid];
    if (tid == 0) v_sh = g_v[r];
    __syncthreads();

    // scores: thread (n, oq) covers o-chunk [oq*32, oq*32+32)
    const int n  = tid & 31;
    const int oq = tid >> 5;
    const float4* obn = obf4 + n * 33 + oq * 8;
    const float4* pb  = (const float4*)p_s;
    float pa0 = 0.0f, pa1 = 0.0f, pa2 = 0.0f, pa3 = 0.0f;
#pragma unroll
    for (int o4 = 0; o4 < 8; o4++) {
        float4 x  = obn[o4];
        float4 p0 = pb[0  + oq * 8 + o4];
        float4 p1 = pb[32 + oq * 8 + o4];
        float4 p2 = pb[64 + oq * 8 + o4];
        float4 p3 = pb[96 + oq * 8 + o4];
        pa0 += x.x * p0.x + x.y * p0.y + x.z * p0.z + x.w * p0.w;
        pa1 += x.x * p1.x + x.y * p1.y + x.z * p1.z + x.w * p1.w;
        pa2 += x.x * p2.x + x.y * p2.y + x.z * p2.z + x.w * p2.w;
        pa3 += x.x * p3.x + x.y * p3.y + x.z * p3.z + x.w * p3.w;
    }
    part_s[oq][0][n] = pa0;
    part_s[oq][1][n] = pa1;
    part_s[oq][2][n] = pa2;
    part_s[oq][3][n] = pa3;
    __syncthreads();

    // softmax per head-warp
    const int h = tid >> 5;
    float s = part_s[0][h][n] + part_s[1][h][n] + part_s[2][h][n] + part_s[3][h][n];
    s *= INV_SQRT_E;
    if (qv_s[n] <= MASK_VAL) s = MASK_VAL;
    float m = s;
#pragma unroll
    for (int d = 16; d > 0; d >>= 1) m = fmaxf(m, __shfl_xor_sync(0xffffffffu, m, d));
    float ex = __expf(s - m);
    float ssum = ex;
#pragma unroll
    for (int d = 16; d > 0; d >>= 1) ssum += __shfl_xor_sync(0xffffffffu, ssum, d);
    att_s[h * 32 + n] = ex / ssum;
    __syncthreads();

    if (tid < 32)
        w_s[tid] = att_s[tid] + att_s[32 + tid] + att_s[64 + tid] + att_s[96 + tid] + 1e-10f;
    __syncthreads();

    if (tid < 64) {
        const float* zsf = (const float*)zf4;  // row stride 68 floats
        float acc = (float)N_DIM * v_sh;
#pragma unroll
        for (int nn = 0; nn < 32; nn++) acc = fmaf(w_s[nn], zsf[nn * 68 + tid], acc);
        out[r * 64 + tid] = acc;
    }
}

// ==================== launch ====================
extern "C" void kernel_launch(void* const* d_in, const int* in_sizes, int n_in,
                              void* d_out, int out_size) {
    (void)in_sizes; (void)n_in; (void)out_size;
    const float* z   = (const float*)d_in[0];
    const float* st  = (const float*)d_in[1];
    const float* obs = (const float*)d_in[2];
    const float* Wq  = (const float*)d_in[3];
    const float* Wk  = (const float*)d_in[4];
    const float* Sw1 = (const float*)d_in[5];
    const float* Sb1 = (const float*)d_in[6];
    const float* Sw2 = (const float*)d_in[7];
    const float* Sb2 = (const float*)d_in[8];
    float* out = (float*)d_out;

    cudaFuncSetAttribute(k1_qh, cudaFuncAttributeMaxDynamicSharedMemorySize, K1_SMEM);
    cudaFuncSetAttribute(k2_p,  cudaFuncAttributeMaxDynamicSharedMemorySize, K2_SMEM);

    k1_qh<<<BT / K1_BM, 256, K1_SMEM>>>(st, Wq, Sw1, Sb1, Sw2, Sb2);
    k2_p<<<BT / K2_BM, 256, K2_SMEM>>>(Wk);
    k3_out<<<BT, 128>>>(z, obs, out);
}